// round 4
// baseline (speedup 1.0000x reference)
#include <cuda_runtime.h>

#define NSEG 256
#define DDIM 256
#define TPB  256
#define MAXN 4096   // scratch capacity in proteins (N=2048 in this problem)

// Per-protein partial sums — overwritten every call, no zeroing required.
__device__ float4 g_partial[MAXN * (DDIM / 4)];   // [N][64] float4 = [N][256] float

// ---------------------------------------------------------------------------
// Kernel A: one block per protein. Each thread strides float4s of this
// protein's [L, D] slab (fully coalesced 128B transactions). Stride 256 over
// 64 float4s/row keeps each thread in column group (tid % 64); the
// cross-thread fold is a 4-way shared-memory sum, then threads 0..63 store
// the protein's 256-float partial-sum row (plain stores, no atomics).
__global__ void __launch_bounds__(TPB) pp_accum_kernel(
    const float4* __restrict__ in,       // [N, L*D/4]
    int vec_per_protein)                 // L*D/4
{
    __shared__ float4 sm[TPB];
    const int n   = blockIdx.x;
    const int tid = threadIdx.x;
    const float4* base = in + (size_t)n * (size_t)vec_per_protein;

    float4 acc = make_float4(0.f, 0.f, 0.f, 0.f);
    #pragma unroll 4
    for (int idx = tid; idx < vec_per_protein; idx += TPB) {
        float4 v = base[idx];
        acc.x += v.x; acc.y += v.y; acc.z += v.z; acc.w += v.w;
    }
    sm[tid] = acc;
    __syncthreads();

    if (tid < 64) {
        float4 a0 = sm[tid];
        float4 a1 = sm[tid + 64];
        float4 a2 = sm[tid + 128];
        float4 a3 = sm[tid + 192];
        float4 r;
        r.x = a0.x + a1.x + a2.x + a3.x;
        r.y = a0.y + a1.y + a2.y + a3.y;
        r.z = a0.z + a1.z + a2.z + a3.z;
        r.w = a0.w + a1.w + a2.w + a3.w;
        g_partial[n * (DDIM / 4) + tid] = r;
    }
}

// ---------------------------------------------------------------------------
// Kernel B: one block per segment. Keys are sorted, so block b finds its
// protein range [lo, hi) by binary search (redundantly in every thread — all
// data L2-hot, no divergence), then thread t sums column t of the matching
// partial rows and writes out[b][t] = acc / ((hi-lo)*L).
//
// Key dtype is detected block-locally: reading the buffer as int32 words,
// int64 values < 256 have all-zero odd words, while sorted int32 keys reach
// 255 at an odd index (some odd word nonzero).
__global__ void __launch_bounds__(TPB) pp_gather_kernel(
    const int* __restrict__ kwords,      // keys viewed as int32 words
    float* __restrict__ out,             // [NSEG, DDIM]
    int nkeys, float Lf)
{
    const int b   = blockIdx.x;
    const int tid = threadIdx.x;

    // dtype detect (block-local, ~8 iterations)
    int local = 0;
    for (int k = tid; k < nkeys; k += TPB)
        if ((k & 1) && kwords[k] != 0) local = 1;
    const int is32 = __syncthreads_or(local);

    // keyAt(n)
    auto keyAt = [&](int n) -> int {
        return is32 ? kwords[n] : kwords[2 * n];   // int64 lo word (values < 256)
    };

    // lower_bound for b and b+1 over sorted keys
    int lo = 0, hi = nkeys;
    {
        int l = 0, r = nkeys;
        while (l < r) { int m = (l + r) >> 1; if (keyAt(m) < b) l = m + 1; else r = m; }
        lo = l;
        l = lo; r = nkeys;
        while (l < r) { int m = (l + r) >> 1; if (keyAt(m) < b + 1) l = m + 1; else r = m; }
        hi = l;
    }

    float acc = 0.0f;
    const float* part = (const float*)g_partial;
    for (int n = lo; n < hi; ++n)
        acc += part[n * DDIM + tid];

    const int cnt = (hi > lo) ? (hi - lo) : 1;   // segments guaranteed non-empty
    out[b * DDIM + tid] = acc / ((float)cnt * Lf);
}

// ---------------------------------------------------------------------------
extern "C" void kernel_launch(void* const* d_in, const int* in_sizes, int n_in,
                              void* d_out, int out_size) {
    // Pick embeds by element count (defend against input-order surprises).
    int ei = 0, ki = 1;
    if (n_in >= 2 && in_sizes[1] > in_sizes[0]) { ei = 1; ki = 0; }

    const float* embeds = (const float*)d_in[ei];   // [N, L, D] fp32
    const int*   kwords = (const int*)d_in[ki];     // [N] int32 or int64 (as words)

    const int N            = in_sizes[ki];
    const int per_protein  = in_sizes[ei] / N;      // L * D
    const int L            = per_protein / DDIM;    // sequence length
    const int vec_per_prot = per_protein / 4;

    pp_accum_kernel<<<N, TPB>>>((const float4*)embeds, vec_per_prot);
    pp_gather_kernel<<<NSEG, TPB>>>(kwords, (float*)d_out, N, (float)L);
}